// round 1
// baseline (speedup 1.0000x reference)
#include <cuda_runtime.h>
#include <math.h>

#define BQ 1024
#define TT 64
#define INDIM 64
#define HH 512
#define LL 8
#define G4 2048
#define CC 128

// ---------------- device scratch (no allocs allowed) ----------------
__device__ float g_P[(size_t)TT * BQ * G4];                    // input projections, [t][b][4H] interleaved
__device__ float g_Hseq[2][(size_t)TT * BQ * HH];              // hidden sequences, ping-pong per layer
__device__ float g_c[BQ * HH];                                 // cell state (per layer, reset at t=0)
__device__ float g_WiT[(size_t)(INDIM + (LL - 1) * HH) * G4];  // interleaved Wi^T, [k][4j+g]
__device__ float g_Wr[(size_t)LL * HH * G4];                   // interleaved Wh^T, [k][4j+g]
__device__ float g_bias[LL * G4];                              // interleaved (b_ih + b_hh)

__device__ __forceinline__ float sigm(float x) { return 1.f / (1.f + __expf(-x)); }

// ---------------- weight prep: interleave gates ----------------
// layout: n = 4*j + g, g in {0:i, 1:f, 2:g, 3:o}, j in [0,512)
__global__ void prep_wr(const float* __restrict__ w_hh0, const float* __restrict__ w_hh) {
    size_t total = (size_t)LL * HH * G4;
    size_t stride = (size_t)gridDim.x * blockDim.x;
    for (size_t idx = (size_t)blockIdx.x * blockDim.x + threadIdx.x; idx < total; idx += stride) {
        int l = (int)(idx / ((size_t)HH * G4));
        int rem = (int)(idx % ((size_t)HH * G4));
        int k = rem / G4, n = rem % G4;
        int j = n >> 2, g = n & 3;
        float v = (l == 0) ? w_hh0[(size_t)(g * HH + j) * HH + k]
                           : w_hh[((size_t)(l - 1) * G4 + g * HH + j) * HH + k];
        g_Wr[idx] = v;
    }
}

__global__ void prep_wi(const float* __restrict__ w_ih0, const float* __restrict__ w_ih) {
    size_t t0 = (size_t)INDIM * G4;
    size_t total = t0 + (size_t)(LL - 1) * HH * G4;
    size_t stride = (size_t)gridDim.x * blockDim.x;
    for (size_t idx = (size_t)blockIdx.x * blockDim.x + threadIdx.x; idx < total; idx += stride) {
        if (idx < t0) {
            int k = (int)(idx / G4), n = (int)(idx % G4);
            int j = n >> 2, g = n & 3;
            g_WiT[idx] = w_ih0[(size_t)(g * HH + j) * INDIM + k];
        } else {
            size_t r = idx - t0;
            int l1 = (int)(r / ((size_t)HH * G4));  // 0..6
            int rem = (int)(r % ((size_t)HH * G4));
            int k = rem / G4, n = rem % G4;
            int j = n >> 2, g = n & 3;
            g_WiT[idx] = w_ih[((size_t)l1 * G4 + g * HH + j) * HH + k];
        }
    }
}

__global__ void prep_bias(const float* __restrict__ b_ih0, const float* __restrict__ b_hh0,
                          const float* __restrict__ b_ih, const float* __restrict__ b_hh) {
    int idx = blockIdx.x * blockDim.x + threadIdx.x;
    if (idx >= LL * G4) return;
    int l = idx / G4, n = idx % G4;
    int j = n >> 2, g = n & 3;
    float v = (l == 0) ? (b_ih0[g * HH + j] + b_hh0[g * HH + j])
                       : (b_ih[(l - 1) * G4 + g * HH + j] + b_hh[(l - 1) * G4 + g * HH + j]);
    g_bias[idx] = v;
}

// ---------------- input projection GEMM ----------------
// P[r][n] = bias_l[n] + sum_k A(r,k) * WiT_l[k][n],  r = t*B + b, over M=65536, N=2048
__global__ void __launch_bounds__(256, 2)
proj_kernel(const float* __restrict__ x, int layer) {
    __shared__ float As[8][132];
    __shared__ float Bs[8][128];

    const int K = (layer == 0) ? INDIM : HH;
    const float* __restrict__ A =
        (layer == 0) ? x : g_Hseq[(layer - 1) & 1];
    const float* __restrict__ Wt =
        g_WiT + ((layer == 0) ? (size_t)0 : (size_t)INDIM * G4 + (size_t)(layer - 1) * HH * G4);
    const float* __restrict__ bias = g_bias + layer * G4;

    const int tid = threadIdx.x;
    const int tx = tid & 15;
    const int ty = tid >> 4;
    const int n0 = blockIdx.x * 128;
    const int r0 = blockIdx.y * 128;

    const int arow = tid >> 1;
    const int acol = (tid & 1) * 4;
    const int brow = tid >> 5;
    const int bcol = (tid & 31) * 4;

    size_t a_base;
    {
        int r = r0 + arow;
        if (layer == 0) { int b = r & (BQ - 1); int t = r >> 10; a_base = (size_t)(b * TT + t) * INDIM; }
        else            a_base = (size_t)r * HH;
    }

    float acc[8][8];
#pragma unroll
    for (int m = 0; m < 8; m++)
#pragma unroll
        for (int n = 0; n < 8; n++) acc[m][n] = 0.f;

    for (int k0 = 0; k0 < K; k0 += 8) {
        float4 av = *(const float4*)(A + a_base + k0 + acol);
        As[acol + 0][arow] = av.x;
        As[acol + 1][arow] = av.y;
        As[acol + 2][arow] = av.z;
        As[acol + 3][arow] = av.w;
        *(float4*)&Bs[brow][bcol] =
            *(const float4*)(Wt + (size_t)(k0 + brow) * G4 + n0 + bcol);
        __syncthreads();
#pragma unroll
        for (int kk = 0; kk < 8; kk++) {
            float4 a0 = *(const float4*)&As[kk][ty * 4];
            float4 a1 = *(const float4*)&As[kk][64 + ty * 4];
            float4 b0 = *(const float4*)&Bs[kk][tx * 4];
            float4 b1 = *(const float4*)&Bs[kk][64 + tx * 4];
            float a[8] = {a0.x, a0.y, a0.z, a0.w, a1.x, a1.y, a1.z, a1.w};
            float bb[8] = {b0.x, b0.y, b0.z, b0.w, b1.x, b1.y, b1.z, b1.w};
#pragma unroll
            for (int m = 0; m < 8; m++)
#pragma unroll
                for (int n = 0; n < 8; n++)
                    acc[m][n] += a[m] * bb[n];
        }
        __syncthreads();
    }

    float4 bb0 = *(const float4*)(bias + n0 + tx * 4);
    float4 bb1 = *(const float4*)(bias + n0 + 64 + tx * 4);
#pragma unroll
    for (int m = 0; m < 8; m++) {
        int rr = r0 + ((m < 4) ? (ty * 4 + m) : (64 + ty * 4 + m - 4));
        float* dst = g_P + (size_t)rr * G4 + n0;
        float4 o0 = make_float4(acc[m][0] + bb0.x, acc[m][1] + bb0.y,
                                acc[m][2] + bb0.z, acc[m][3] + bb0.w);
        float4 o1 = make_float4(acc[m][4] + bb1.x, acc[m][5] + bb1.y,
                                acc[m][6] + bb1.z, acc[m][7] + bb1.w);
        *(float4*)(dst + tx * 4) = o0;
        *(float4*)(dst + 64 + tx * 4) = o1;
    }
}

// ---------------- fused recurrent step: gates GEMM + LSTM cell ----------------
// gates[b][n] = P[t][b][n] + sum_k h_prev[b][k] * Wr_l[k][n]; then cell update.
__global__ void __launch_bounds__(256, 2)
recur_kernel(int layer, int t) {
    __shared__ float As[8][132];
    __shared__ float Bs[8][128];

    const int t0 = (t == 0);
    float* __restrict__ Hbuf = g_Hseq[layer & 1];
    const float* __restrict__ hprev = Hbuf + (size_t)(t - 1) * BQ * HH;  // unused at t==0
    float* __restrict__ hout = Hbuf + (size_t)t * BQ * HH;
    const float* __restrict__ Wr = g_Wr + (size_t)layer * HH * G4;
    const float* __restrict__ Pt = g_P + (size_t)t * BQ * G4;

    const int tid = threadIdx.x;
    const int tx = tid & 15;
    const int ty = tid >> 4;
    const int n0 = blockIdx.x * 128;
    const int r0 = blockIdx.y * 128;

    const int arow = tid >> 1;
    const int acol = (tid & 1) * 4;
    const int brow = tid >> 5;
    const int bcol = (tid & 31) * 4;

    float acc[8][8];
#pragma unroll
    for (int m = 0; m < 8; m++)
#pragma unroll
        for (int n = 0; n < 8; n++) acc[m][n] = 0.f;

    if (!t0) {
        size_t a_base = (size_t)(r0 + arow) * HH;
        for (int k0 = 0; k0 < HH; k0 += 8) {
            float4 av = *(const float4*)(hprev + a_base + k0 + acol);
            As[acol + 0][arow] = av.x;
            As[acol + 1][arow] = av.y;
            As[acol + 2][arow] = av.z;
            As[acol + 3][arow] = av.w;
            *(float4*)&Bs[brow][bcol] =
                *(const float4*)(Wr + (size_t)(k0 + brow) * G4 + n0 + bcol);
            __syncthreads();
#pragma unroll
            for (int kk = 0; kk < 8; kk++) {
                float4 a0 = *(const float4*)&As[kk][ty * 4];
                float4 a1 = *(const float4*)&As[kk][64 + ty * 4];
                float4 b0 = *(const float4*)&Bs[kk][tx * 4];
                float4 b1 = *(const float4*)&Bs[kk][64 + tx * 4];
                float a[8] = {a0.x, a0.y, a0.z, a0.w, a1.x, a1.y, a1.z, a1.w};
                float bb[8] = {b0.x, b0.y, b0.z, b0.w, b1.x, b1.y, b1.z, b1.w};
#pragma unroll
                for (int m = 0; m < 8; m++)
#pragma unroll
                    for (int n = 0; n < 8; n++)
                        acc[m][n] += a[m] * bb[n];
            }
            __syncthreads();
        }
    }

    const int jx0 = (n0 >> 2) + tx;
    const int jx1 = (n0 >> 2) + 16 + tx;
#pragma unroll
    for (int m = 0; m < 8; m++) {
        int b = r0 + ((m < 4) ? (ty * 4 + m) : (64 + ty * 4 + m - 4));
        const float* Prow = Pt + (size_t)b * G4 + n0;
        float4 p0 = *(const float4*)(Prow + tx * 4);
        float4 p1 = *(const float4*)(Prow + 64 + tx * 4);
        {
            float iv = sigm(acc[m][0] + p0.x);
            float fv = sigm(acc[m][1] + p0.y);
            float gv = tanhf(acc[m][2] + p0.z);
            float ov = sigm(acc[m][3] + p0.w);
            float cp = t0 ? 0.f : g_c[b * HH + jx0];
            float cn = fv * cp + iv * gv;
            g_c[b * HH + jx0] = cn;
            hout[(size_t)b * HH + jx0] = ov * tanhf(cn);
        }
        {
            float iv = sigm(acc[m][4] + p1.x);
            float fv = sigm(acc[m][5] + p1.y);
            float gv = tanhf(acc[m][6] + p1.z);
            float ov = sigm(acc[m][7] + p1.w);
            float cp = t0 ? 0.f : g_c[b * HH + jx1];
            float cn = fv * cp + iv * gv;
            g_c[b * HH + jx1] = cn;
            hout[(size_t)b * HH + jx1] = ov * tanhf(cn);
        }
    }
}

// ---------------- final FC ----------------
__global__ void fc_init(const float* __restrict__ fc_b, float* __restrict__ out) {
    int i = blockIdx.x * blockDim.x + threadIdx.x;
    if (i < BQ * CC) out[i] = fc_b[i & (CC - 1)];
}

// out[b][c] += sum_j Hseq[t][b][j] * fc_w[c][t*512+j]  (split-K over t, atomics)
__global__ void __launch_bounds__(256, 2)
fc_kernel(const float* __restrict__ fw, float* __restrict__ out) {
    __shared__ float As[8][132];
    __shared__ float Bs[8][132];

    const float* __restrict__ Hs = g_Hseq[(LL - 1) & 1];
    const int tid = threadIdx.x;
    const int tx = tid & 15;
    const int ty = tid >> 4;
    const int r0 = blockIdx.x * 128;
    const int t = blockIdx.y;

    const int arow = tid >> 1;
    const int acol = (tid & 1) * 4;
    const int crow = tid >> 1;        // output channel
    const int ckq = (tid & 1) * 4;    // k quad

    size_t a_base = (size_t)t * BQ * HH + (size_t)(r0 + arow) * HH;
    size_t b_base = (size_t)crow * (TT * HH) + (size_t)t * HH;

    float acc[8][8];
#pragma unroll
    for (int m = 0; m < 8; m++)
#pragma unroll
        for (int n = 0; n < 8; n++) acc[m][n] = 0.f;

    for (int k0 = 0; k0 < HH; k0 += 8) {
        float4 av = *(const float4*)(Hs + a_base + k0 + acol);
        As[acol + 0][arow] = av.x;
        As[acol + 1][arow] = av.y;
        As[acol + 2][arow] = av.z;
        As[acol + 3][arow] = av.w;
        float4 bv = *(const float4*)(fw + b_base + k0 + ckq);
        Bs[ckq + 0][crow] = bv.x;
        Bs[ckq + 1][crow] = bv.y;
        Bs[ckq + 2][crow] = bv.z;
        Bs[ckq + 3][crow] = bv.w;
        __syncthreads();
#pragma unroll
        for (int kk = 0; kk < 8; kk++) {
            float4 a0 = *(const float4*)&As[kk][ty * 4];
            float4 a1 = *(const float4*)&As[kk][64 + ty * 4];
            float4 b0 = *(const float4*)&Bs[kk][tx * 4];
            float4 b1 = *(const float4*)&Bs[kk][64 + tx * 4];
            float a[8] = {a0.x, a0.y, a0.z, a0.w, a1.x, a1.y, a1.z, a1.w};
            float bb[8] = {b0.x, b0.y, b0.z, b0.w, b1.x, b1.y, b1.z, b1.w};
#pragma unroll
            for (int m = 0; m < 8; m++)
#pragma unroll
                for (int n = 0; n < 8; n++)
                    acc[m][n] += a[m] * bb[n];
        }
        __syncthreads();
    }

#pragma unroll
    for (int m = 0; m < 8; m++) {
        int rr = r0 + ((m < 4) ? (ty * 4 + m) : (64 + ty * 4 + m - 4));
#pragma unroll
        for (int n = 0; n < 4; n++) {
            atomicAdd(out + rr * CC + tx * 4 + n, acc[m][n]);
            atomicAdd(out + rr * CC + 64 + tx * 4 + n, acc[m][n + 4]);
        }
    }
}

// ---------------- launch ----------------
extern "C" void kernel_launch(void* const* d_in, const int* in_sizes, int n_in,
                              void* d_out, int out_size) {
    const float* x     = (const float*)d_in[0];
    const float* w_ih0 = (const float*)d_in[1];
    const float* w_hh0 = (const float*)d_in[2];
    const float* b_ih0 = (const float*)d_in[3];
    const float* b_hh0 = (const float*)d_in[4];
    const float* w_ih  = (const float*)d_in[5];
    const float* w_hh  = (const float*)d_in[6];
    const float* b_ih  = (const float*)d_in[7];
    const float* b_hh  = (const float*)d_in[8];
    const float* fc_w  = (const float*)d_in[9];
    const float* fc_b  = (const float*)d_in[10];
    float* out = (float*)d_out;

    prep_wr<<<4096, 256>>>(w_hh0, w_hh);
    prep_wi<<<4096, 256>>>(w_ih0, w_ih);
    prep_bias<<<64, 256>>>(b_ih0, b_hh0, b_ih, b_hh);

    for (int l = 0; l < LL; l++) {
        proj_kernel<<<dim3(G4 / 128, (TT * BQ) / 128), 256>>>(x, l);
        for (int t = 0; t < TT; t++) {
            recur_kernel<<<dim3(G4 / 128, BQ / 128), 256>>>(l, t);
        }
    }

    fc_init<<<(BQ * CC + 255) / 256, 256>>>(fc_b, out);
    fc_kernel<<<dim3(BQ / 128, TT), 256>>>(fc_w, out);
}

// round 2
// speedup vs baseline: 1.6179x; 1.6179x over previous
#include <cuda_runtime.h>
#include <math.h>
#include <stdint.h>

#define BQ 1024
#define TT 64
#define INDIM 64
#define HH 512
#define LL 8
#define G4 2048
#define CC 128
#define NBLK 128

// ---------------- device scratch ----------------
__device__ float g_P[(size_t)TT * BQ * G4];                    // input projections, [t][b][4H] interleaved
__device__ float g_Hseq[2][(size_t)TT * BQ * HH];              // hidden sequences, ping-pong per layer
__device__ float g_WiT[(size_t)(INDIM + (LL - 1) * HH) * G4];  // interleaved Wi^T, [k][4j+g]
__device__ float g_WrF[(size_t)LL * HH * G4];                  // tf32 Wr in mma-B fragment layout
__device__ float g_bias[LL * G4];                              // interleaved (b_ih + b_hh)
__device__ int g_bar_count;                                    // zero-init
__device__ volatile int g_phase;                               // zero-init, monotonic

__device__ __forceinline__ float sigm(float x) { return 1.f / (1.f + __expf(-x)); }

__device__ __forceinline__ uint32_t f2tf(float x) {
    uint32_t r;
    asm("cvt.rna.tf32.f32 %0, %1;" : "=r"(r) : "f"(x));
    return r;
}

__device__ __forceinline__ void cp16(void* dst, const void* src) {
    uint32_t d = (uint32_t)__cvta_generic_to_shared(dst);
    asm volatile("cp.async.cg.shared.global [%0], [%1], 16;" ::"r"(d), "l"(src));
}

__device__ __forceinline__ void mma8(float* c, const uint32_t* a, uint32_t b0, uint32_t b1) {
    asm volatile(
        "mma.sync.aligned.m16n8k8.row.col.f32.tf32.tf32.f32 "
        "{%0,%1,%2,%3}, {%4,%5,%6,%7}, {%8,%9}, {%0,%1,%2,%3};"
        : "+f"(c[0]), "+f"(c[1]), "+f"(c[2]), "+f"(c[3])
        : "r"(a[0]), "r"(a[1]), "r"(a[2]), "r"(a[3]), "r"(b0), "r"(b1));
}

// ---------------- weight prep ----------------
// Wr fragment layout per layer: [k8(64)][n8(256)][lane(32)][2], value = Wr[k][n],
// n = 4j+g interleave; b0: k=lane%4, n=lane/4; b1: k=lane%4+4. tf32-rounded.
__global__ void prep_wr(const float* __restrict__ w_hh0, const float* __restrict__ w_hh) {
    size_t total = (size_t)LL * HH * G4;
    size_t stride = (size_t)gridDim.x * blockDim.x;
    for (size_t idx = (size_t)blockIdx.x * blockDim.x + threadIdx.x; idx < total; idx += stride) {
        int l = (int)(idx / ((size_t)HH * G4));
        int rem = (int)(idx % ((size_t)HH * G4));
        int k8 = rem / (256 * 64);
        int r2 = rem % (256 * 64);
        int n8 = r2 / 64;
        int q = r2 % 64;
        int lane = q >> 1, rr = q & 1;
        int n = n8 * 8 + (lane >> 2);
        int k = k8 * 8 + (lane & 3) + 4 * rr;
        int j = n >> 2, g = n & 3;
        float v = (l == 0) ? w_hh0[(size_t)(g * HH + j) * HH + k]
                           : w_hh[((size_t)(l - 1) * G4 + g * HH + j) * HH + k];
        g_WrF[idx] = __uint_as_float(f2tf(v));
    }
}

__global__ void prep_wi(const float* __restrict__ w_ih0, const float* __restrict__ w_ih) {
    size_t t0 = (size_t)INDIM * G4;
    size_t total = t0 + (size_t)(LL - 1) * HH * G4;
    size_t stride = (size_t)gridDim.x * blockDim.x;
    for (size_t idx = (size_t)blockIdx.x * blockDim.x + threadIdx.x; idx < total; idx += stride) {
        if (idx < t0) {
            int k = (int)(idx / G4), n = (int)(idx % G4);
            int j = n >> 2, g = n & 3;
            g_WiT[idx] = w_ih0[(size_t)(g * HH + j) * INDIM + k];
        } else {
            size_t r = idx - t0;
            int l1 = (int)(r / ((size_t)HH * G4));
            int rem = (int)(r % ((size_t)HH * G4));
            int k = rem / G4, n = rem % G4;
            int j = n >> 2, g = n & 3;
            g_WiT[idx] = w_ih[((size_t)l1 * G4 + g * HH + j) * HH + k];
        }
    }
}

__global__ void prep_bias(const float* __restrict__ b_ih0, const float* __restrict__ b_hh0,
                          const float* __restrict__ b_ih, const float* __restrict__ b_hh) {
    int idx = blockIdx.x * blockDim.x + threadIdx.x;
    if (idx >= LL * G4) return;
    int l = idx / G4, n = idx % G4;
    int j = n >> 2, g = n & 3;
    float v = (l == 0) ? (b_ih0[g * HH + j] + b_hh0[g * HH + j])
                       : (b_ih[(l - 1) * G4 + g * HH + j] + b_hh[(l - 1) * G4 + g * HH + j]);
    g_bias[idx] = v;
}

// ---------------- input projection GEMM (fp32, unchanged) ----------------
__global__ void __launch_bounds__(256, 2)
proj_kernel(const float* __restrict__ x, int layer) {
    __shared__ float As[8][132];
    __shared__ float Bs[8][128];

    const int K = (layer == 0) ? INDIM : HH;
    const float* __restrict__ A = (layer == 0) ? x : g_Hseq[(layer - 1) & 1];
    const float* __restrict__ Wt =
        g_WiT + ((layer == 0) ? (size_t)0 : (size_t)INDIM * G4 + (size_t)(layer - 1) * HH * G4);
    const float* __restrict__ bias = g_bias + layer * G4;

    const int tid = threadIdx.x;
    const int tx = tid & 15;
    const int ty = tid >> 4;
    const int n0 = blockIdx.x * 128;
    const int r0 = blockIdx.y * 128;

    const int arow = tid >> 1;
    const int acol = (tid & 1) * 4;
    const int brow = tid >> 5;
    const int bcol = (tid & 31) * 4;

    size_t a_base;
    {
        int r = r0 + arow;
        if (layer == 0) { int b = r & (BQ - 1); int t = r >> 10; a_base = (size_t)(b * TT + t) * INDIM; }
        else            a_base = (size_t)r * HH;
    }

    float acc[8][8];
#pragma unroll
    for (int m = 0; m < 8; m++)
#pragma unroll
        for (int n = 0; n < 8; n++) acc[m][n] = 0.f;

    for (int k0 = 0; k0 < K; k0 += 8) {
        float4 av = *(const float4*)(A + a_base + k0 + acol);
        As[acol + 0][arow] = av.x;
        As[acol + 1][arow] = av.y;
        As[acol + 2][arow] = av.z;
        As[acol + 3][arow] = av.w;
        *(float4*)&Bs[brow][bcol] =
            *(const float4*)(Wt + (size_t)(k0 + brow) * G4 + n0 + bcol);
        __syncthreads();
#pragma unroll
        for (int kk = 0; kk < 8; kk++) {
            float4 a0 = *(const float4*)&As[kk][ty * 4];
            float4 a1 = *(const float4*)&As[kk][64 + ty * 4];
            float4 b0 = *(const float4*)&Bs[kk][tx * 4];
            float4 b1 = *(const float4*)&Bs[kk][64 + tx * 4];
            float a[8] = {a0.x, a0.y, a0.z, a0.w, a1.x, a1.y, a1.z, a1.w};
            float bb[8] = {b0.x, b0.y, b0.z, b0.w, b1.x, b1.y, b1.z, b1.w};
#pragma unroll
            for (int m = 0; m < 8; m++)
#pragma unroll
                for (int n = 0; n < 8; n++)
                    acc[m][n] += a[m] * bb[n];
        }
        __syncthreads();
    }

    float4 bb0 = *(const float4*)(bias + n0 + tx * 4);
    float4 bb1 = *(const float4*)(bias + n0 + 64 + tx * 4);
#pragma unroll
    for (int m = 0; m < 8; m++) {
        int rr = r0 + ((m < 4) ? (ty * 4 + m) : (64 + ty * 4 + m - 4));
        float* dst = g_P + (size_t)rr * G4 + n0;
        float4 o0 = make_float4(acc[m][0] + bb0.x, acc[m][1] + bb0.y,
                                acc[m][2] + bb0.z, acc[m][3] + bb0.w);
        float4 o1 = make_float4(acc[m][4] + bb1.x, acc[m][5] + bb1.y,
                                acc[m][6] + bb1.z, acc[m][7] + bb1.w);
        *(float4*)(dst + tx * 4) = o0;
        *(float4*)(dst + 64 + tx * 4) = o1;
    }
}

// ---------------- persistent recurrent layer: tf32 tensor-core GEMM + fused cell ----------------
// grid (16, 8): blockIdx.x -> N tile (128 cols), blockIdx.y -> M tile (128 batch rows)
// smem: sA[2][128*36] fp32 h-chunk (K=32), sW[2][4096] fragment-ready Wr chunk.
__device__ __forceinline__ void grid_bar(int target) {
    __threadfence();
    __syncthreads();
    if (threadIdx.x == 0) {
        int v = atomicAdd(&g_bar_count, 1);
        if (v == NBLK - 1) {
            g_bar_count = 0;
            __threadfence();
            g_phase = target;
        } else {
            while (g_phase < target) __nanosleep(32);
        }
    }
    __syncthreads();
}

__global__ void __launch_bounds__(256, 1) recur_persist(int layer) {
    extern __shared__ float sm[];
    float* sA = sm;             // 2 * 4608 floats (128 rows x stride 36)
    float* sW = sm + 2 * 4608;  // 2 * 4096 floats

    const int tid = threadIdx.x;
    const int lane = tid & 31, wid = tid >> 5;
    const int warpM = wid >> 1, warpN = wid & 1;  // 4 x 2 warps
    const int n0 = blockIdx.x * 128;
    const int r0 = blockIdx.y * 128;
    const int n8base = blockIdx.x * 16;
    const int g = lane >> 2, tig = lane & 3;
    const int rowoff = g + ((tig & 1) ? 8 : 0);
    const int jj = tig >> 1;
    const int srow = tid >> 1, scol = (tid & 1) * 16;

    float* Hbuf = g_Hseq[layer & 1];
    const float* __restrict__ WrL = g_WrF + (size_t)layer * HH * G4;
    int base = g_phase;  // quiesced: all blocks read the same value

    float cst[2][8];
#pragma unroll
    for (int mt = 0; mt < 2; mt++)
#pragma unroll
        for (int nt = 0; nt < 8; nt++) cst[mt][nt] = 0.f;

    const float* hp = nullptr;
    auto load_chunk = [&](int kc, int s) {
        const float* gsrc = hp + (size_t)(r0 + srow) * HH + kc * 32 + scol;
        float* adst = sA + s * 4608 + srow * 36 + scol;
#pragma unroll
        for (int i = 0; i < 4; i++) cp16(adst + i * 4, gsrc + i * 4);
#pragma unroll
        for (int i = 0; i < 4; i++) {
            int k8g = kc * 4 + i;
            const float* ws = WrL + ((size_t)k8g * 256 + n8base) * 64 + tid * 4;
            cp16(sW + s * 4096 + i * 1024 + tid * 4, ws);
        }
        asm volatile("cp.async.commit_group;" ::: "memory");
    };

    for (int t = 0; t < TT; t++) {
        float acc[2][8][4];
#pragma unroll
        for (int mt = 0; mt < 2; mt++)
#pragma unroll
            for (int nt = 0; nt < 8; nt++)
#pragma unroll
                for (int q = 0; q < 4; q++) acc[mt][nt][q] = 0.f;

        if (t > 0) {
            hp = Hbuf + (size_t)(t - 1) * BQ * HH;
            load_chunk(0, 0);
            for (int kc = 0; kc < 16; kc++) {
                int cur = kc & 1;
                if (kc < 15) {
                    load_chunk(kc + 1, cur ^ 1);
                    asm volatile("cp.async.wait_group 1;" ::: "memory");
                } else {
                    asm volatile("cp.async.wait_group 0;" ::: "memory");
                }
                __syncthreads();
                const float* sa = sA + cur * 4608;
                const float* swc = sW + cur * 4096;
#pragma unroll
                for (int k8 = 0; k8 < 4; k8++) {
                    uint32_t afr[2][4];
#pragma unroll
                    for (int mt = 0; mt < 2; mt++) {
                        int mb = warpM * 32 + mt * 16;
                        const float* b0p = sa + (mb + g) * 36 + k8 * 8 + tig;
                        const float* b1p = sa + (mb + g + 8) * 36 + k8 * 8 + tig;
                        afr[mt][0] = f2tf(b0p[0]);
                        afr[mt][2] = f2tf(b0p[4]);
                        afr[mt][1] = f2tf(b1p[0]);
                        afr[mt][3] = f2tf(b1p[4]);
                    }
                    const float* swp = swc + (k8 * 16 + warpN * 8) * 64 + lane * 2;
#pragma unroll
                    for (int nt = 0; nt < 8; nt++) {
                        float2 bv = *(const float2*)(swp + nt * 64);
                        uint32_t b0 = __float_as_uint(bv.x);
                        uint32_t b1 = __float_as_uint(bv.y);
                        mma8(acc[0][nt], afr[0], b0, b1);
                        mma8(acc[1][nt], afr[1], b0, b1);
                    }
                }
                __syncthreads();
            }
        }

        // fused LSTM cell epilogue
        const float* __restrict__ Pt = g_P + (size_t)t * BQ * G4;
        float* hout = Hbuf + (size_t)t * BQ * HH;
#pragma unroll
        for (int mt = 0; mt < 2; mt++) {
            int b = r0 + warpM * 32 + mt * 16 + rowoff;
            float* hrow = hout + (size_t)b * HH;
            const float* prow = Pt + (size_t)b * G4;
#pragma unroll
            for (int nt = 0; nt < 8; nt++) {
                float c0 = acc[mt][nt][0], c1 = acc[mt][nt][1];
                float c2 = acc[mt][nt][2], c3 = acc[mt][nt][3];
                float d0 = __shfl_xor_sync(0xffffffffu, c0, 1);
                float d1 = __shfl_xor_sync(0xffffffffu, c1, 1);
                float d2 = __shfl_xor_sync(0xffffffffu, c2, 1);
                float d3 = __shfl_xor_sync(0xffffffffu, c3, 1);
                float gi, gf, gg, go;
                if ((tig & 1) == 0) { gi = c0; gf = c1; gg = d0; go = d1; }
                else                { gi = d2; gf = d3; gg = c2; go = c3; }
                int j = ((n0 + warpN * 64 + nt * 8) >> 2) + jj;
                float4 p = *(const float4*)(prow + 4 * j);
                gi = sigm(gi + p.x);
                gf = sigm(gf + p.y);
                gg = tanhf(gg + p.z);
                go = sigm(go + p.w);
                float c = gf * cst[mt][nt] + gi * gg;
                cst[mt][nt] = c;
                hrow[j] = go * tanhf(c);
            }
        }
        grid_bar(base + t + 1);
    }
}

// ---------------- final FC ----------------
__global__ void fc_init(const float* __restrict__ fc_b, float* __restrict__ out) {
    int i = blockIdx.x * blockDim.x + threadIdx.x;
    if (i < BQ * CC) out[i] = fc_b[i & (CC - 1)];
}

__global__ void __launch_bounds__(256, 2)
fc_kernel(const float* __restrict__ fw, float* __restrict__ out) {
    __shared__ float As[8][132];
    __shared__ float Bs[8][132];

    const float* __restrict__ Hs = g_Hseq[(LL - 1) & 1];
    const int tid = threadIdx.x;
    const int tx = tid & 15;
    const int ty = tid >> 4;
    const int r0 = blockIdx.x * 128;
    const int t = blockIdx.y;

    const int arow = tid >> 1;
    const int acol = (tid & 1) * 4;
    const int crow = tid >> 1;
    const int ckq = (tid & 1) * 4;

    size_t a_base = (size_t)t * BQ * HH + (size_t)(r0 + arow) * HH;
    size_t b_base = (size_t)crow * (TT * HH) + (size_t)t * HH;

    float acc[8][8];
#pragma unroll
    for (int m = 0; m < 8; m++)
#pragma unroll
        for (int n = 0; n < 8; n++) acc[m][n] = 0.f;

    for (int k0 = 0; k0 < HH; k0 += 8) {
        float4 av = *(const float4*)(Hs + a_base + k0 + acol);
        As[acol + 0][arow] = av.x;
        As[acol + 1][arow] = av.y;
        As[acol + 2][arow] = av.z;
        As[acol + 3][arow] = av.w;
        float4 bv = *(const float4*)(fw + b_base + k0 + ckq);
        Bs[ckq + 0][crow] = bv.x;
        Bs[ckq + 1][crow] = bv.y;
        Bs[ckq + 2][crow] = bv.z;
        Bs[ckq + 3][crow] = bv.w;
        __syncthreads();
#pragma unroll
        for (int kk = 0; kk < 8; kk++) {
            float4 a0 = *(const float4*)&As[kk][ty * 4];
            float4 a1 = *(const float4*)&As[kk][64 + ty * 4];
            float4 b0 = *(const float4*)&Bs[kk][tx * 4];
            float4 b1 = *(const float4*)&Bs[kk][64 + tx * 4];
            float a[8] = {a0.x, a0.y, a0.z, a0.w, a1.x, a1.y, a1.z, a1.w};
            float bb[8] = {b0.x, b0.y, b0.z, b0.w, b1.x, b1.y, b1.z, b1.w};
#pragma unroll
            for (int m = 0; m < 8; m++)
#pragma unroll
                for (int n = 0; n < 8; n++)
                    acc[m][n] += a[m] * bb[n];
        }
        __syncthreads();
    }

#pragma unroll
    for (int m = 0; m < 8; m++) {
        int rr = r0 + ((m < 4) ? (ty * 4 + m) : (64 + ty * 4 + m - 4));
#pragma unroll
        for (int n = 0; n < 4; n++) {
            atomicAdd(out + rr * CC + tx * 4 + n, acc[m][n]);
            atomicAdd(out + rr * CC + 64 + tx * 4 + n, acc[m][n + 4]);
        }
    }
}

// ---------------- launch ----------------
extern "C" void kernel_launch(void* const* d_in, const int* in_sizes, int n_in,
                              void* d_out, int out_size) {
    const float* x     = (const float*)d_in[0];
    const float* w_ih0 = (const float*)d_in[1];
    const float* w_hh0 = (const float*)d_in[2];
    const float* b_ih0 = (const float*)d_in[3];
    const float* b_hh0 = (const float*)d_in[4];
    const float* w_ih  = (const float*)d_in[5];
    const float* w_hh  = (const float*)d_in[6];
    const float* b_ih  = (const float*)d_in[7];
    const float* b_hh  = (const float*)d_in[8];
    const float* fc_w  = (const float*)d_in[9];
    const float* fc_b  = (const float*)d_in[10];
    float* out = (float*)d_out;

    const int smem_bytes = (2 * 4608 + 2 * 4096) * 4;  // 69632
    cudaFuncSetAttribute(recur_persist, cudaFuncAttributeMaxDynamicSharedMemorySize, smem_bytes);

    prep_wr<<<4096, 256>>>(w_hh0, w_hh);
    prep_wi<<<4096, 256>>>(w_ih0, w_ih);
    prep_bias<<<64, 256>>>(b_ih0, b_hh0, b_ih, b_hh);

    for (int l = 0; l < LL; l++) {
        proj_kernel<<<dim3(G4 / 128, (TT * BQ) / 128), 256>>>(x, l);
        recur_persist<<<dim3(16, 8), 256, smem_bytes>>>(l);
    }

    fc_init<<<(BQ * CC + 255) / 256, 256>>>(fc_b, out);
    fc_kernel<<<dim3(BQ / 128, TT), 256>>>(fc_w, out);
}

// round 4
// speedup vs baseline: 4.5349x; 2.8030x over previous
#include <cuda_runtime.h>
#include <cuda_fp16.h>
#include <math.h>
#include <stdint.h>

#define BQ 1024
#define TT 64
#define INDIM 64
#define LL 8
#define HHD 512
#define G4 2048
#define CC 128
#define NBLK 128

// ---------------- device scratch ----------------
__device__ float g_P[(size_t)TT * BQ * G4];                       // gate preactivations (x-part + bias), permuted cols
__device__ __align__(128) __half g_H16[2][(size_t)TT * BQ * HHD]; // hidden seq fp16, ping-pong
__device__ __align__(128) __half g_X16[(size_t)TT * BQ * INDIM];  // x as fp16, [t*B+b][k]
__device__ __align__(128) uint32_t g_WiH[((size_t)INDIM + (LL - 1) * HHD) * G4 / 2]; // Wi fragments
__device__ __align__(128) uint32_t g_WrH[(size_t)LL * HHD * G4 / 2];                 // Wr fragments
__device__ float g_bias[LL * G4];
__device__ int g_bar_count;
__device__ volatile int g_phase;

__device__ __forceinline__ float sigm(float x) { return __fdividef(1.f, 1.f + __expf(-x)); }
__device__ __forceinline__ float tnh(float x) {
    float e = __expf(2.f * x);
    return 1.f - __fdividef(2.f, e + 1.f);
}

__device__ __forceinline__ void cp16(void* dst, const void* src) {
    uint32_t d = (uint32_t)__cvta_generic_to_shared(dst);
    asm volatile("cp.async.cg.shared.global [%0], [%1], 16;" ::"r"(d), "l"(src));
}

__device__ __forceinline__ void mma16(float* c, const uint32_t* a, uint32_t b0, uint32_t b1) {
    asm volatile(
        "mma.sync.aligned.m16n8k16.row.col.f32.f16.f16.f32 "
        "{%0,%1,%2,%3}, {%4,%5,%6,%7}, {%8,%9}, {%0,%1,%2,%3};"
        : "+f"(c[0]), "+f"(c[1]), "+f"(c[2]), "+f"(c[3])
        : "r"(a[0]), "r"(a[1]), "r"(a[2]), "r"(a[3]), "r"(b0), "r"(b1));
}

// column permutation: n_log(g, j) = (j>>5)*128 + ((j>>3)&3)*32 + g*8 + (j&7)
// inverse: j = (n>>7)*32 + ((n>>5)&3)*8 + (n&7); g = (n>>3)&3

// ---------------- weight prep: fp16 fragment images ----------------
// flat uint32 index: ((k16*256 + n8)*64 + lane*2 + r); half2 = W[k0][n], W[k0+1][n]
// with k0 = k16*16 + (lane&3)*2 + r*8, n = n8*8 + (lane>>2)
__global__ void prep_wi(const float* __restrict__ w_ih0, const float* __restrict__ w_ih) {
    const size_t R0 = (size_t)INDIM * G4 / 2;  // 65536
    size_t total = R0 + (size_t)(LL - 1) * HHD * G4 / 2;
    size_t stride = (size_t)gridDim.x * blockDim.x;
    for (size_t idx = (size_t)blockIdx.x * blockDim.x + threadIdx.x; idx < total; idx += stride) {
        int l;
        uint32_t rem;
        if (idx < R0) { l = 0; rem = (uint32_t)idx; }
        else { size_t r = idx - R0; l = 1 + (int)(r >> 19); rem = (uint32_t)(r & 524287u); }
        int rr = rem & 1, lane = (rem >> 1) & 31, n8 = (rem >> 6) & 255, k16 = rem >> 14;
        int k0 = k16 * 16 + (lane & 3) * 2 + rr * 8;
        int nlog = n8 * 8 + (lane >> 2);
        int j = ((nlog >> 7) << 5) + (((nlog >> 5) & 3) << 3) + (nlog & 7);
        int g = (nlog >> 3) & 3;
        float v0, v1;
        if (l == 0) {
            const float* p = w_ih0 + (size_t)(g * HHD + j) * INDIM + k0;
            v0 = p[0]; v1 = p[1];
        } else {
            const float* p = w_ih + ((size_t)(l - 1) * G4 + g * HHD + j) * HHD + k0;
            v0 = p[0]; v1 = p[1];
        }
        __half2 h = __floats2half2_rn(v0, v1);
        g_WiH[idx] = *(uint32_t*)&h;
    }
}

__global__ void prep_wr(const float* __restrict__ w_hh0, const float* __restrict__ w_hh) {
    size_t total = (size_t)LL * HHD * G4 / 2;
    size_t stride = (size_t)gridDim.x * blockDim.x;
    for (size_t idx = (size_t)blockIdx.x * blockDim.x + threadIdx.x; idx < total; idx += stride) {
        int l = (int)(idx >> 19);
        uint32_t rem = (uint32_t)(idx & 524287u);
        int rr = rem & 1, lane = (rem >> 1) & 31, n8 = (rem >> 6) & 255, k16 = rem >> 14;
        int k0 = k16 * 16 + (lane & 3) * 2 + rr * 8;
        int nlog = n8 * 8 + (lane >> 2);
        int j = ((nlog >> 7) << 5) + (((nlog >> 5) & 3) << 3) + (nlog & 7);
        int g = (nlog >> 3) & 3;
        float v0, v1;
        if (l == 0) {
            const float* p = w_hh0 + (size_t)(g * HHD + j) * HHD + k0;
            v0 = p[0]; v1 = p[1];
        } else {
            const float* p = w_hh + ((size_t)(l - 1) * G4 + g * HHD + j) * HHD + k0;
            v0 = p[0]; v1 = p[1];
        }
        __half2 h = __floats2half2_rn(v0, v1);
        g_WrH[idx] = *(uint32_t*)&h;
    }
}

__global__ void prep_bias(const float* __restrict__ b_ih0, const float* __restrict__ b_hh0,
                          const float* __restrict__ b_ih, const float* __restrict__ b_hh) {
    int idx = blockIdx.x * blockDim.x + threadIdx.x;
    if (idx >= LL * G4) return;
    int l = idx >> 11, nlog = idx & 2047;
    int j = ((nlog >> 7) << 5) + (((nlog >> 5) & 3) << 3) + (nlog & 7);
    int g = (nlog >> 3) & 3;
    float v = (l == 0) ? (b_ih0[g * HHD + j] + b_hh0[g * HHD + j])
                       : (b_ih[(l - 1) * G4 + g * HHD + j] + b_hh[(l - 1) * G4 + g * HHD + j]);
    g_bias[idx] = v;
}

__global__ void prep_x(const float* __restrict__ x) {
    size_t total = (size_t)TT * BQ * INDIM;
    size_t stride = (size_t)gridDim.x * blockDim.x;
    for (size_t idx = (size_t)blockIdx.x * blockDim.x + threadIdx.x; idx < total; idx += stride) {
        int k = (int)(idx & 63);
        int r = (int)(idx >> 6);
        int b = r & (BQ - 1), t = r >> 10;
        g_X16[idx] = __float2half(x[((size_t)b * TT + t) * INDIM + k]);
    }
}

// ---------------- shared GEMM-chunk machinery ----------------
// smem: sA[2][128*72] halves (36864 B) + sB[2][4096] uint32 (32768 B) = 69632 B
#define SMEM_BYTES 69632
#define SA_STRIDE 72

// ---------------- input projection: fp16 tensor GEMM ----------------
__global__ void __launch_bounds__(256, 1) proj16(int layer) {
    extern __shared__ char smem[];
    __half* sA = (__half*)smem;
    uint32_t* sB = (uint32_t*)(smem + 36864);

    const int tid = threadIdx.x, lane = tid & 31, wid = tid >> 5;
    const int warpM = wid >> 2, warpN = wid & 3;
    const int n8base = blockIdx.x * 16;
    const int n0 = blockIdx.x * 128;
    const int r0 = blockIdx.y * 128;
    const int K = (layer == 0) ? INDIM : HHD;
    const int NC = K / 64;
    const __half* __restrict__ A = (layer == 0) ? g_X16 : g_H16[(layer - 1) & 1];
    const uint32_t* __restrict__ W =
        g_WiH + ((layer == 0) ? (size_t)0 : (size_t)(INDIM * G4 / 2) + (size_t)(layer - 1) * (HHD * G4 / 2));

    float acc[4][4][4];
#pragma unroll
    for (int mt = 0; mt < 4; mt++)
#pragma unroll
        for (int nt = 0; nt < 4; nt++)
#pragma unroll
            for (int q = 0; q < 4; q++) acc[mt][nt][q] = 0.f;

    auto load = [&](int kc, int s) {
        __half* sa = sA + s * 9216;
#pragma unroll
        for (int i = 0; i < 4; i++) {
            int u = i * 256 + tid;
            int row = u >> 3, seg = u & 7;
            cp16(sa + row * SA_STRIDE + seg * 8, A + (size_t)(r0 + row) * K + kc * 64 + seg * 8);
        }
        uint32_t* sb = sB + s * 4096;
#pragma unroll
        for (int k16l = 0; k16l < 4; k16l++) {
            cp16(sb + k16l * 1024 + tid * 4,
                 W + ((size_t)(kc * 4 + k16l) * 256 + n8base) * 64 + tid * 4);
        }
        asm volatile("cp.async.commit_group;" ::: "memory");
    };

    load(0, 0);
    if (NC > 1) load(1, 1);
    for (int kc = 0; kc < NC; kc++) {
        int s = kc & 1;
        if (kc + 2 <= NC) asm volatile("cp.async.wait_group 1;" ::: "memory");
        else              asm volatile("cp.async.wait_group 0;" ::: "memory");
        __syncthreads();
        const __half* sa = sA + s * 9216;
        const uint32_t* sb = sB + s * 4096;
#pragma unroll
        for (int k16l = 0; k16l < 4; k16l++) {
            uint32_t a[4][4];
#pragma unroll
            for (int mt = 0; mt < 4; mt++) {
                int m = warpM * 64 + mt * 16 + (lane >> 2);
                const __half* ap = sa + m * SA_STRIDE + k16l * 16 + (lane & 3) * 2;
                a[mt][0] = *(const uint32_t*)ap;
                a[mt][1] = *(const uint32_t*)(ap + 8 * SA_STRIDE);
                a[mt][2] = *(const uint32_t*)(ap + 8);
                a[mt][3] = *(const uint32_t*)(ap + 8 * SA_STRIDE + 8);
            }
#pragma unroll
            for (int nt = 0; nt < 4; nt++) {
                uint2 b = *(const uint2*)(sb + (k16l * 16 + warpN * 4 + nt) * 64 + lane * 2);
#pragma unroll
                for (int mt = 0; mt < 4; mt++) mma16(acc[mt][nt], a[mt], b.x, b.y);
            }
        }
        __syncthreads();
        if (kc + 2 < NC) load(kc + 2, s);
    }

    const float* __restrict__ bias = g_bias + layer * G4;
#pragma unroll
    for (int nt = 0; nt < 4; nt++) {
        int ncol = n0 + warpN * 32 + nt * 8 + (lane & 3) * 2;
        float2 bv = *(const float2*)&bias[ncol];
#pragma unroll
        for (int mt = 0; mt < 4; mt++) {
            int row = r0 + warpM * 64 + mt * 16 + (lane >> 2);
            float2 o0 = make_float2(acc[mt][nt][0] + bv.x, acc[mt][nt][1] + bv.y);
            float2 o1 = make_float2(acc[mt][nt][2] + bv.x, acc[mt][nt][3] + bv.y);
            *(float2*)&g_P[(size_t)row * G4 + ncol] = o0;
            *(float2*)&g_P[(size_t)(row + 8) * G4 + ncol] = o1;
        }
    }
}

// ---------------- grid barrier ----------------
__device__ __forceinline__ void grid_bar(int target) {
    __threadfence();
    __syncthreads();
    if (threadIdx.x == 0) {
        int v = atomicAdd(&g_bar_count, 1);
        if (v == NBLK - 1) {
            g_bar_count = 0;
            __threadfence();
            g_phase = target;
        } else {
            while (g_phase < target) __nanosleep(32);
        }
    }
    __syncthreads();
}

// ---------------- persistent recurrent layer: fp16 tensor GEMM + fused cell ----------------
__global__ void __launch_bounds__(256, 1) recur16(int layer) {
    extern __shared__ char smem[];
    __half* sA = (__half*)smem;
    uint32_t* sB = (uint32_t*)(smem + 36864);

    const int tid = threadIdx.x, lane = tid & 31, wid = tid >> 5;
    const int warpM = wid >> 2, warpN = wid & 3;
    const int n8base = blockIdx.x * 16;
    const int n0 = blockIdx.x * 128;
    const int r0 = blockIdx.y * 128;

    __half* Hbuf = g_H16[layer & 1];
    const uint32_t* __restrict__ W = g_WrH + (size_t)layer * (HHD * G4 / 2);
    const int base = g_phase;

    float cst[4][2][2];
#pragma unroll
    for (int mt = 0; mt < 4; mt++)
#pragma unroll
        for (int rr = 0; rr < 2; rr++) { cst[mt][rr][0] = 0.f; cst[mt][rr][1] = 0.f; }

    const int j0 = blockIdx.x * 32 + warpN * 8 + (lane & 3) * 2;

    for (int t = 0; t < TT; t++) {
        float acc[4][4][4];
#pragma unroll
        for (int mt = 0; mt < 4; mt++)
#pragma unroll
            for (int nt = 0; nt < 4; nt++)
#pragma unroll
                for (int q = 0; q < 4; q++) acc[mt][nt][q] = 0.f;

        if (t > 0) {
            const __half* __restrict__ A = Hbuf + (size_t)(t - 1) * BQ * HHD;
            auto load = [&](int kc, int s) {
                __half* sa = sA + s * 9216;
#pragma unroll
                for (int i = 0; i < 4; i++) {
                    int u = i * 256 + tid;
                    int row = u >> 3, seg = u & 7;
                    cp16(sa + row * SA_STRIDE + seg * 8,
                         A + (size_t)(r0 + row) * HHD + kc * 64 + seg * 8);
                }
                uint32_t* sb = sB + s * 4096;
#pragma unroll
                for (int k16l = 0; k16l < 4; k16l++) {
                    cp16(sb + k16l * 1024 + tid * 4,
                         W + ((size_t)(kc * 4 + k16l) * 256 + n8base) * 64 + tid * 4);
                }
                asm volatile("cp.async.commit_group;" ::: "memory");
            };

            load(0, 0);
            load(1, 1);
            for (int kc = 0; kc < 8; kc++) {
                int s = kc & 1;
                if (kc < 6) asm volatile("cp.async.wait_group 1;" ::: "memory");
                else        asm volatile("cp.async.wait_group 0;" ::: "memory");
                __syncthreads();
                const __half* sa = sA + s * 9216;
                const uint32_t* sb = sB + s * 4096;
#pragma unroll
                for (int k16l = 0; k16l < 4; k16l++) {
                    uint32_t a[4][4];
#pragma unroll
                    for (int mt = 0; mt < 4; mt++) {
                        int m = warpM * 64 + mt * 16 + (lane >> 2);
                        const __half* ap = sa + m * SA_STRIDE + k16l * 16 + (lane & 3) * 2;
                        a[mt][0] = *(const uint32_t*)ap;
                        a[mt][1] = *(const uint32_t*)(ap + 8 * SA_STRIDE);
                        a[mt][2] = *(const uint32_t*)(ap + 8);
                        a[mt][3] = *(const uint32_t*)(ap + 8 * SA_STRIDE + 8);
                    }
#pragma unroll
                    for (int nt = 0; nt < 4; nt++) {
                        uint2 b = *(const uint2*)(sb + (k16l * 16 + warpN * 4 + nt) * 64 + lane * 2);
#pragma unroll
                        for (int mt = 0; mt < 4; mt++) mma16(acc[mt][nt], a[mt], b.x, b.y);
                    }
                }
                __syncthreads();
                if (kc + 2 < 8) load(kc + 2, s);
            }
        }

        // fused LSTM cell epilogue: nt == gate, thread owns 2 adjacent cells
        const float* __restrict__ Pt = g_P + (size_t)t * BQ * G4;
        __half* hout = Hbuf + (size_t)t * BQ * HHD;
#pragma unroll
        for (int mt = 0; mt < 4; mt++) {
#pragma unroll
            for (int rr = 0; rr < 2; rr++) {
                int b = r0 + warpM * 64 + mt * 16 + (lane >> 2) + rr * 8;
                const float* prow = Pt + (size_t)b * G4 + n0 + warpN * 32 + (lane & 3) * 2;
                float2 pi = *(const float2*)(prow);
                float2 pf = *(const float2*)(prow + 8);
                float2 pg = *(const float2*)(prow + 16);
                float2 po = *(const float2*)(prow + 24);
                float i0 = sigm(acc[mt][0][rr * 2 + 0] + pi.x);
                float i1 = sigm(acc[mt][0][rr * 2 + 1] + pi.y);
                float f0 = sigm(acc[mt][1][rr * 2 + 0] + pf.x);
                float f1 = sigm(acc[mt][1][rr * 2 + 1] + pf.y);
                float gg0 = tnh(acc[mt][2][rr * 2 + 0] + pg.x);
                float gg1 = tnh(acc[mt][2][rr * 2 + 1] + pg.y);
                float o0 = sigm(acc[mt][3][rr * 2 + 0] + po.x);
                float o1 = sigm(acc[mt][3][rr * 2 + 1] + po.y);
                float c0 = f0 * cst[mt][rr][0] + i0 * gg0;
                float c1 = f1 * cst[mt][rr][1] + i1 * gg1;
                cst[mt][rr][0] = c0;
                cst[mt][rr][1] = c1;
                __half2 hv = __floats2half2_rn(o0 * tnh(c0), o1 * tnh(c1));
                *(__half2*)&hout[(size_t)b * HHD + j0] = hv;
            }
        }
        grid_bar(base + t + 1);
    }
}

// ---------------- final FC ----------------
__global__ void fc_init(const float* __restrict__ fc_b, float* __restrict__ out) {
    int i = blockIdx.x * blockDim.x + threadIdx.x;
    if (i < BQ * CC) out[i] = fc_b[i & (CC - 1)];
}

__global__ void __launch_bounds__(256, 2)
fc_kernel(const float* __restrict__ fw, float* __restrict__ out) {
    __shared__ float As[8][132];
    __shared__ float Bs[8][132];

    const __half* __restrict__ Hs = g_H16[(LL - 1) & 1];
    const int tid = threadIdx.x;
    const int tx = tid & 15;
    const int ty = tid >> 4;
    const int r0 = blockIdx.x * 128;
    const int t = blockIdx.y;

    const int arow = tid >> 1;
    const int acol = (tid & 1) * 4;
    const int crow = tid >> 1;
    const int ckq = (tid & 1) * 4;

    size_t a_base = (size_t)t * BQ * HHD + (size_t)(r0 + arow) * HHD;
    size_t b_base = (size_t)crow * (TT * HHD) + (size_t)t * HHD;

    float acc[8][8];
#pragma unroll
    for (int m = 0; m < 8; m++)
#pragma unroll
        for (int n = 0; n < 8; n++) acc[m][n] = 0.f;

    for (int k0 = 0; k0 < HHD; k0 += 8) {
        uint2 hv = *(const uint2*)(Hs + a_base + k0 + acol);
        float2 f01 = __half22float2(*(__half2*)&hv.x);
        float2 f23 = __half22float2(*(__half2*)&hv.y);
        As[acol + 0][arow] = f01.x;
        As[acol + 1][arow] = f01.y;
        As[acol + 2][arow] = f23.x;
        As[acol + 3][arow] = f23.y;
        float4 bv = *(const float4*)(fw + b_base + k0 + ckq);
        Bs[ckq + 0][crow] = bv.x;
        Bs[ckq + 1][crow] = bv.y;
        Bs[ckq + 2][crow] = bv.z;
        Bs[ckq + 3][crow] = bv.w;
        __syncthreads();
#pragma unroll
        for (int kk = 0; kk < 8; kk++) {
            float4 a0 = *(const float4*)&As[kk][ty * 4];
            float4 a1 = *(const float4*)&As[kk][64 + ty * 4];
            float4 b0 = *(const float4*)&Bs[kk][tx * 4];
            float4 b1 = *(const float4*)&Bs[kk][64 + tx * 4];
            float a[8] = {a0.x, a0.y, a0.z, a0.w, a1.x, a1.y, a1.z, a1.w};
            float bb[8] = {b0.x, b0.y, b0.z, b0.w, b1.x, b1.y, b1.z, b1.w};
#pragma unroll
            for (int m = 0; m < 8; m++)
#pragma unroll
                for (int n = 0; n < 8; n++)
                    acc[m][n] += a[m] * bb[n];
        }
        __syncthreads();
    }

#pragma unroll
    for (int m = 0; m < 8; m++) {
        int rr = r0 + ((m < 4) ? (ty * 4 + m) : (64 + ty * 4 + m - 4));
#pragma unroll
        for (int n = 0; n < 4; n++) {
            atomicAdd(out + rr * CC + tx * 4 + n, acc[m][n]);
            atomicAdd(out + rr * CC + 64 + tx * 4 + n, acc[m][n + 4]);
        }
    }
}

// ---------------- launch ----------------
extern "C" void kernel_launch(void* const* d_in, const int* in_sizes, int n_in,
                              void* d_out, int out_size) {
    const float* x     = (const float*)d_in[0];
    const float* w_ih0 = (const float*)d_in[1];
    const float* w_hh0 = (const float*)d_in[2];
    const float* b_ih0 = (const float*)d_in[3];
    const float* b_hh0 = (const float*)d_in[4];
    const float* w_ih  = (const float*)d_in[5];
    const float* w_hh  = (const float*)d_in[6];
    const float* b_ih  = (const float*)d_in[7];
    const float* b_hh  = (const float*)d_in[8];
    const float* fc_w  = (const float*)d_in[9];
    const float* fc_b  = (const float*)d_in[10];
    float* out = (float*)d_out;

    cudaFuncSetAttribute(proj16, cudaFuncAttributeMaxDynamicSharedMemorySize, SMEM_BYTES);
    cudaFuncSetAttribute(recur16, cudaFuncAttributeMaxDynamicSharedMemorySize, SMEM_BYTES);

    prep_x<<<2048, 256>>>(x);
    prep_wi<<<4096, 256>>>(w_ih0, w_ih);
    prep_wr<<<4096, 256>>>(w_hh0, w_hh);
    prep_bias<<<64, 256>>>(b_ih0, b_hh0, b_ih, b_hh);

    for (int l = 0; l < LL; l++) {
        proj16<<<dim3(16, 512), 256, SMEM_BYTES>>>(l);
        recur16<<<dim3(16, 8), 256, SMEM_BYTES>>>(l);
    }

    fc_init<<<(BQ * CC + 255) / 256, 256>>>(fc_b, out);
    fc_kernel<<<dim3(BQ / 128, TT), 256>>>(fc_w, out);
}

// round 6
// speedup vs baseline: 6.5029x; 1.4340x over previous
#include <cuda_runtime.h>
#include <cuda_fp16.h>
#include <math.h>
#include <stdint.h>

#define BQ 1024
#define TT 64
#define INDIM 64
#define LL 8
#define HHD 512
#define G4 2048
#define CC 128
#define NBLK 128

// ---------------- device scratch ----------------
__device__ __align__(128) __half g_P16[(size_t)TT * BQ * G4];      // gate preactivations fp16, permuted cols
__device__ __align__(128) __half g_H16[2][(size_t)TT * BQ * HHD];  // hidden seq fp16, ping-pong
__device__ __align__(128) __half g_X16[(size_t)TT * BQ * INDIM];   // x as fp16, [t*B+b][k]
__device__ __align__(128) uint32_t g_WiH[((size_t)INDIM + (LL - 1) * HHD) * G4 / 2]; // Wi fragments
__device__ __align__(128) uint32_t g_WrH[(size_t)LL * HHD * G4 / 2];                 // Wr fragments
__device__ float g_bias[LL * G4];
__device__ int g_bar_count;
__device__ volatile int g_phase;

__device__ __forceinline__ float sigm(float x) { return __fdividef(1.f, 1.f + __expf(-x)); }
__device__ __forceinline__ float tnh(float x) {
    float e = __expf(2.f * x);
    return 1.f - __fdividef(2.f, e + 1.f);
}

__device__ __forceinline__ void cp16(void* dst, const void* src) {
    uint32_t d = (uint32_t)__cvta_generic_to_shared(dst);
    asm volatile("cp.async.cg.shared.global [%0], [%1], 16;" ::"r"(d), "l"(src));
}

__device__ __forceinline__ void mma16(float* c, const uint32_t* a, uint32_t b0, uint32_t b1) {
    asm volatile(
        "mma.sync.aligned.m16n8k16.row.col.f32.f16.f16.f32 "
        "{%0,%1,%2,%3}, {%4,%5,%6,%7}, {%8,%9}, {%0,%1,%2,%3};"
        : "+f"(c[0]), "+f"(c[1]), "+f"(c[2]), "+f"(c[3])
        : "r"(a[0]), "r"(a[1]), "r"(a[2]), "r"(a[3]), "r"(b0), "r"(b1));
}

__device__ __forceinline__ void ldmat4(uint32_t* a, uint32_t addr) {
    asm volatile(
        "ldmatrix.sync.aligned.m8n8.x4.shared.b16 {%0,%1,%2,%3}, [%4];"
        : "=r"(a[0]), "=r"(a[1]), "=r"(a[2]), "=r"(a[3]) : "r"(addr));
}

// column permutation: n_log(g, j) = (j>>5)*128 + ((j>>3)&3)*32 + g*8 + (j&7)

// ---------------- weight prep: fp16 fragment images ----------------
__global__ void prep_wi(const float* __restrict__ w_ih0, const float* __restrict__ w_ih) {
    const size_t R0 = (size_t)INDIM * G4 / 2;
    size_t total = R0 + (size_t)(LL - 1) * HHD * G4 / 2;
    size_t stride = (size_t)gridDim.x * blockDim.x;
    for (size_t idx = (size_t)blockIdx.x * blockDim.x + threadIdx.x; idx < total; idx += stride) {
        int l;
        uint32_t rem;
        if (idx < R0) { l = 0; rem = (uint32_t)idx; }
        else { size_t r = idx - R0; l = 1 + (int)(r >> 19); rem = (uint32_t)(r & 524287u); }
        int rr = rem & 1, lane = (rem >> 1) & 31, n8 = (rem >> 6) & 255, k16 = rem >> 14;
        int k0 = k16 * 16 + (lane & 3) * 2 + rr * 8;
        int nlog = n8 * 8 + (lane >> 2);
        int j = ((nlog >> 7) << 5) + (((nlog >> 5) & 3) << 3) + (nlog & 7);
        int g = (nlog >> 3) & 3;
        float v0, v1;
        if (l == 0) {
            const float* p = w_ih0 + (size_t)(g * HHD + j) * INDIM + k0;
            v0 = p[0]; v1 = p[1];
        } else {
            const float* p = w_ih + ((size_t)(l - 1) * G4 + g * HHD + j) * HHD + k0;
            v0 = p[0]; v1 = p[1];
        }
        __half2 h = __floats2half2_rn(v0, v1);
        g_WiH[idx] = *(uint32_t*)&h;
    }
}

__global__ void prep_wr(const float* __restrict__ w_hh0, const float* __restrict__ w_hh) {
    size_t total = (size_t)LL * HHD * G4 / 2;
    size_t stride = (size_t)gridDim.x * blockDim.x;
    for (size_t idx = (size_t)blockIdx.x * blockDim.x + threadIdx.x; idx < total; idx += stride) {
        int l = (int)(idx >> 19);
        uint32_t rem = (uint32_t)(idx & 524287u);
        int rr = rem & 1, lane = (rem >> 1) & 31, n8 = (rem >> 6) & 255, k16 = rem >> 14;
        int k0 = k16 * 16 + (lane & 3) * 2 + rr * 8;
        int nlog = n8 * 8 + (lane >> 2);
        int j = ((nlog >> 7) << 5) + (((nlog >> 5) & 3) << 3) + (nlog & 7);
        int g = (nlog >> 3) & 3;
        float v0, v1;
        if (l == 0) {
            const float* p = w_hh0 + (size_t)(g * HHD + j) * HHD + k0;
            v0 = p[0]; v1 = p[1];
        } else {
            const float* p = w_hh + ((size_t)(l - 1) * G4 + g * HHD + j) * HHD + k0;
            v0 = p[0]; v1 = p[1];
        }
        __half2 h = __floats2half2_rn(v0, v1);
        g_WrH[idx] = *(uint32_t*)&h;
    }
}

__global__ void prep_bias(const float* __restrict__ b_ih0, const float* __restrict__ b_hh0,
                          const float* __restrict__ b_ih, const float* __restrict__ b_hh) {
    int idx = blockIdx.x * blockDim.x + threadIdx.x;
    if (idx >= LL * G4) return;
    int l = idx >> 11, nlog = idx & 2047;
    int j = ((nlog >> 7) << 5) + (((nlog >> 5) & 3) << 3) + (nlog & 7);
    int g = (nlog >> 3) & 3;
    float v = (l == 0) ? (b_ih0[g * HHD + j] + b_hh0[g * HHD + j])
                       : (b_ih[(l - 1) * G4 + g * HHD + j] + b_hh[(l - 1) * G4 + g * HHD + j]);
    g_bias[idx] = v;
}

__global__ void prep_x(const float* __restrict__ x) {
    size_t total = (size_t)TT * BQ * INDIM;
    size_t stride = (size_t)gridDim.x * blockDim.x;
    for (size_t idx = (size_t)blockIdx.x * blockDim.x + threadIdx.x; idx < total; idx += stride) {
        int k = (int)(idx & 63);
        int r = (int)(idx >> 6);
        int b = r & (BQ - 1), t = r >> 10;
        g_X16[idx] = __float2half(x[((size_t)b * TT + t) * INDIM + k]);
    }
}

// smem layout (bytes): sA[2][128*64 halves] = 32768, sB[2][4096 u32] = 32768,
// sP (recur only) 128 rows x 136-half stride (272B, 16B-aligned, 4-bank row shift) = 34816
#define SB_OFF 32768
#define SP_OFF 65536
#define SP_STRIDE 136
#define PROJ_SMEM 65536
#define RECUR_SMEM (65536 + 128 * SP_STRIDE * 2)

// ---------------- input projection: fp16 tensor GEMM ----------------
__global__ void __launch_bounds__(256, 2) proj16(int layer) {
    extern __shared__ char smem[];
    __half* sA = (__half*)smem;
    uint32_t* sB = (uint32_t*)(smem + SB_OFF);
    const uint32_t saddr = (uint32_t)__cvta_generic_to_shared(smem);

    const int tid = threadIdx.x, lane = tid & 31, wid = tid >> 5;
    const int warpM = wid >> 2, warpN = wid & 3;
    const int n8base = blockIdx.x * 16;
    const int n0 = blockIdx.x * 128;
    const int r0 = blockIdx.y * 128;
    const int K = (layer == 0) ? INDIM : HHD;
    const int NC = K / 64;
    const __half* __restrict__ A = (layer == 0) ? g_X16 : g_H16[(layer - 1) & 1];
    const uint32_t* __restrict__ W =
        g_WiH + ((layer == 0) ? (size_t)0 : (size_t)(INDIM * G4 / 2) + (size_t)(layer - 1) * (HHD * G4 / 2));

    const int quad = lane >> 3, rr8 = lane & 7;
    const int gsel = quad >> 1;
    const uint32_t abase = saddr + (uint32_t)(warpM * 64 + rr8 + (quad & 1) * 8) * 128;

    float acc[4][4][4];
#pragma unroll
    for (int mt = 0; mt < 4; mt++)
#pragma unroll
        for (int nt = 0; nt < 4; nt++)
#pragma unroll
            for (int q = 0; q < 4; q++) acc[mt][nt][q] = 0.f;

    auto load = [&](int kc, int s) {
        __half* sa = sA + s * 8192;
#pragma unroll
        for (int i = 0; i < 4; i++) {
            int u = i * 256 + tid;
            int row = u >> 3, seg = u & 7;
            cp16(sa + row * 64 + (seg ^ (row & 7)) * 8,
                 A + (size_t)(r0 + row) * K + kc * 64 + seg * 8);
        }
        uint32_t* sb = sB + s * 4096;
#pragma unroll
        for (int k16l = 0; k16l < 4; k16l++) {
            cp16(sb + k16l * 1024 + tid * 4,
                 W + ((size_t)(kc * 4 + k16l) * 256 + n8base) * 64 + tid * 4);
        }
        asm volatile("cp.async.commit_group;" ::: "memory");
    };

    load(0, 0);
    if (NC > 1) load(1, 1);
    for (int kc = 0; kc < NC; kc++) {
        int s = kc & 1;
        if (kc + 2 <= NC) asm volatile("cp.async.wait_group 1;" ::: "memory");
        else              asm volatile("cp.async.wait_group 0;" ::: "memory");
        __syncthreads();
        const uint32_t sa_u = abase + s * 16384;
        const uint32_t* sb = sB + s * 4096;
#pragma unroll
        for (int k16l = 0; k16l < 4; k16l++) {
            const uint32_t grp = (uint32_t)(((k16l * 2 + gsel) ^ rr8) * 16);
            uint32_t a[4][4];
#pragma unroll
            for (int mt = 0; mt < 4; mt++) ldmat4(a[mt], sa_u + mt * 2048 + grp);
#pragma unroll
            for (int nt = 0; nt < 4; nt++) {
                uint2 b = *(const uint2*)(sb + (k16l * 16 + warpN * 4 + nt) * 64 + lane * 2);
#pragma unroll
                for (int mt = 0; mt < 4; mt++) mma16(acc[mt][nt], a[mt], b.x, b.y);
            }
        }
        __syncthreads();
        if (kc + 2 < NC) load(kc + 2, s);
    }

    const float* __restrict__ bias = g_bias + layer * G4;
#pragma unroll
    for (int nt = 0; nt < 4; nt++) {
        int ncol = n0 + warpN * 32 + nt * 8 + (lane & 3) * 2;
        float2 bv = *(const float2*)&bias[ncol];
#pragma unroll
        for (int mt = 0; mt < 4; mt++) {
            int row = r0 + warpM * 64 + mt * 16 + (lane >> 2);
            *(__half2*)&g_P16[(size_t)row * G4 + ncol] =
                __floats2half2_rn(acc[mt][nt][0] + bv.x, acc[mt][nt][1] + bv.y);
            *(__half2*)&g_P16[(size_t)(row + 8) * G4 + ncol] =
                __floats2half2_rn(acc[mt][nt][2] + bv.x, acc[mt][nt][3] + bv.y);
        }
    }
}

// ---------------- grid barrier ----------------
__device__ __forceinline__ void grid_bar(int target) {
    __threadfence();
    __syncthreads();
    if (threadIdx.x == 0) {
        int v = atomicAdd(&g_bar_count, 1);
        if (v == NBLK - 1) {
            g_bar_count = 0;
            __threadfence();
            g_phase = target;
        } else {
            while (g_phase < target) __nanosleep(32);
        }
    }
    __syncthreads();
}

// ---------------- persistent recurrent layer ----------------
__global__ void __launch_bounds__(256, 1) recur16(int layer) {
    extern __shared__ char smem[];
    __half* sA = (__half*)smem;
    uint32_t* sB = (uint32_t*)(smem + SB_OFF);
    __half* sP = (__half*)(smem + SP_OFF);
    const uint32_t saddr = (uint32_t)__cvta_generic_to_shared(smem);

    const int tid = threadIdx.x, lane = tid & 31, wid = tid >> 5;
    const int warpM = wid >> 2, warpN = wid & 3;
    const int n8base = blockIdx.x * 16;
    const int n0 = blockIdx.x * 128;
    const int r0 = blockIdx.y * 128;

    __half* Hbuf = g_H16[layer & 1];
    const uint32_t* __restrict__ W = g_WrH + (size_t)layer * (HHD * G4 / 2);
    const int base = g_phase;

    const int quad = lane >> 3, rr8 = lane & 7;
    const int gsel = quad >> 1;
    const uint32_t abase = saddr + (uint32_t)(warpM * 64 + rr8 + (quad & 1) * 8) * 128;

    float cst[4][2][2];
#pragma unroll
    for (int mt = 0; mt < 4; mt++)
#pragma unroll
        for (int rr = 0; rr < 2; rr++) { cst[mt][rr][0] = 0.f; cst[mt][rr][1] = 0.f; }

    const int j0 = blockIdx.x * 32 + warpN * 8 + (lane & 3) * 2;

    for (int t = 0; t < TT; t++) {
        // prefetch P tile into smem (joins first commit group)
        {
            const __half* Pg = g_P16 + (size_t)t * BQ * G4;
#pragma unroll
            for (int i = 0; i < 8; i++) {
                int u = i * 256 + tid;
                int row = u >> 4, seg = u & 15;
                cp16(sP + row * SP_STRIDE + seg * 8,
                     Pg + (size_t)(r0 + row) * G4 + n0 + seg * 8);
            }
        }

        float acc[4][4][4];
#pragma unroll
        for (int mt = 0; mt < 4; mt++)
#pragma unroll
            for (int nt = 0; nt < 4; nt++)
#pragma unroll
                for (int q = 0; q < 4; q++) acc[mt][nt][q] = 0.f;

        if (t > 0) {
            const __half* __restrict__ A = Hbuf + (size_t)(t - 1) * BQ * HHD;
            auto load = [&](int kc, int s) {
                __half* sa = sA + s * 8192;
#pragma unroll
                for (int i = 0; i < 4; i++) {
                    int u = i * 256 + tid;
                    int row = u >> 3, seg = u & 7;
                    cp16(sa + row * 64 + (seg ^ (row & 7)) * 8,
                         A + (size_t)(r0 + row) * HHD + kc * 64 + seg * 8);
                }
                uint32_t* sb = sB + s * 4096;
#pragma unroll
                for (int k16l = 0; k16l < 4; k16l++) {
                    cp16(sb + k16l * 1024 + tid * 4,
                         W + ((size_t)(kc * 4 + k16l) * 256 + n8base) * 64 + tid * 4);
                }
                asm volatile("cp.async.commit_group;" ::: "memory");
            };

            load(0, 0);
            load(1, 1);
            for (int kc = 0; kc < 8; kc++) {
                int s = kc & 1;
                if (kc < 6) asm volatile("cp.async.wait_group 1;" ::: "memory");
                else        asm volatile("cp.async.wait_group 0;" ::: "memory");
                __syncthreads();
                const uint32_t sa_u = abase + s * 16384;
                const uint32_t* sb = sB + s * 4096;
#pragma unroll
                for (int k16l = 0; k16l < 4; k16l++) {
                    const uint32_t grp = (uint32_t)(((k16l * 2 + gsel) ^ rr8) * 16);
                    uint32_t a[4][4];
#pragma unroll
                    for (int mt = 0; mt < 4; mt++) ldmat4(a[mt], sa_u + mt * 2048 + grp);
#pragma unroll
                    for (int nt = 0; nt < 4; nt++) {
                        uint2 b = *(const uint2*)(sb + (k16l * 16 + warpN * 4 + nt) * 64 + lane * 2);
#pragma unroll
                        for (int mt = 0; mt < 4; mt++) mma16(acc[mt][nt], a[mt], b.x, b.y);
                    }
                }
                __syncthreads();
                if (kc + 2 < 8) load(kc + 2, s);
            }
        } else {
            asm volatile("cp.async.commit_group;" ::: "memory");
            asm volatile("cp.async.wait_group 0;" ::: "memory");
            __syncthreads();
        }

        // fused LSTM cell epilogue (P from smem)
        __half* hout = Hbuf + (size_t)t * BQ * HHD;
#pragma unroll
        for (int mt = 0; mt < 4; mt++) {
#pragma unroll
            for (int rr = 0; rr < 2; rr++) {
                int lrow = warpM * 64 + mt * 16 + (lane >> 2) + rr * 8;
                const __half* prow = sP + (size_t)lrow * SP_STRIDE + warpN * 32 + (lane & 3) * 2;
                float2 pi = __half22float2(*(const __half2*)(prow));
                float2 pf = __half22float2(*(const __half2*)(prow + 8));
                float2 pg = __half22float2(*(const __half2*)(prow + 16));
                float2 po = __half22float2(*(const __half2*)(prow + 24));
                float i0 = sigm(acc[mt][0][rr * 2 + 0] + pi.x);
                float i1 = sigm(acc[mt][0][rr * 2 + 1] + pi.y);
                float f0 = sigm(acc[mt][1][rr * 2 + 0] + pf.x);
                float f1 = sigm(acc[mt][1][rr * 2 + 1] + pf.y);
                float gg0 = tnh(acc[mt][2][rr * 2 + 0] + pg.x);
                float gg1 = tnh(acc[mt][2][rr * 2 + 1] + pg.y);
                float o0 = sigm(acc[mt][3][rr * 2 + 0] + po.x);
                float o1 = sigm(acc[mt][3][rr * 2 + 1] + po.y);
                float c0 = f0 * cst[mt][rr][0] + i0 * gg0;
                float c1 = f1 * cst[mt][rr][1] + i1 * gg1;
                cst[mt][rr][0] = c0;
                cst[mt][rr][1] = c1;
                int b = r0 + lrow;
                *(__half2*)&hout[(size_t)b * HHD + j0] =
                    __floats2half2_rn(o0 * tnh(c0), o1 * tnh(c1));
            }
        }
        grid_bar(base + t + 1);
    }
}

// ---------------- final FC ----------------
__global__ void fc_init(const float* __restrict__ fc_b, float* __restrict__ out) {
    int i = blockIdx.x * blockDim.x + threadIdx.x;
    if (i < BQ * CC) out[i] = fc_b[i & (CC - 1)];
}

__global__ void __launch_bounds__(256, 2)
fc_kernel(const float* __restrict__ fw, float* __restrict__ out) {
    __shared__ float As[8][132];
    __shared__ float Bs[8][132];

    const __half* __restrict__ Hs = g_H16[(LL - 1) & 1];
    const int tid = threadIdx.x;
    const int tx = tid & 15;
    const int ty = tid >> 4;
    const int r0 = blockIdx.x * 128;
    const int t = blockIdx.y;

    const int arow = tid >> 1;
    const int acol = (tid & 1) * 4;
    const int crow = tid >> 1;
    const int ckq = (tid & 1) * 4;

    size_t a_base = (size_t)t * BQ * HHD + (size_t)(r0 + arow) * HHD;
    size_t b_base = (size_t)crow * (TT * HHD) + (size_t)t * HHD;

    float acc[8][8];
#pragma unroll
    for (int m = 0; m < 8; m++)
#pragma unroll
        for (int n = 0; n < 8; n++) acc[m][n] = 0.f;

    for (int k0 = 0; k0 < HHD; k0 += 8) {
        uint2 hv = *(const uint2*)(Hs + a_base + k0 + acol);
        float2 f01 = __half22float2(*(__half2*)&hv.x);
        float2 f23 = __half22float2(*(__half2*)&hv.y);
        As[acol + 0][arow] = f01.x;
        As[acol + 1][arow] = f01.y;
        As[acol + 2][arow] = f23.x;
        As[acol + 3][arow] = f23.y;
        float4 bv = *(const float4*)(fw + b_base + k0 + ckq);
        Bs[ckq + 0][crow] = bv.x;
        Bs[ckq + 1][crow] = bv.y;
        Bs[ckq + 2][crow] = bv.z;
        Bs[ckq + 3][crow] = bv.w;
        __syncthreads();
#pragma unroll
        for (int kk = 0; kk < 8; kk++) {
            float4 a0 = *(const float4*)&As[kk][ty * 4];
            float4 a1 = *(const float4*)&As[kk][64 + ty * 4];
            float4 b0 = *(const float4*)&Bs[kk][tx * 4];
            float4 b1 = *(const float4*)&Bs[kk][64 + tx * 4];
            float a[8] = {a0.x, a0.y, a0.z, a0.w, a1.x, a1.y, a1.z, a1.w};
            float bb[8] = {b0.x, b0.y, b0.z, b0.w, b1.x, b1.y, b1.z, b1.w};
#pragma unroll
            for (int m = 0; m < 8; m++)
#pragma unroll
                for (int n = 0; n < 8; n++)
                    acc[m][n] += a[m] * bb[n];
        }
        __syncthreads();
    }

#pragma unroll
    for (int m = 0; m < 8; m++) {
        int rr = r0 + ((m < 4) ? (ty * 4 + m) : (64 + ty * 4 + m - 4));
#pragma unroll
        for (int n = 0; n < 4; n++) {
            atomicAdd(out + rr * CC + tx * 4 + n, acc[m][n]);
            atomicAdd(out + rr * CC + 64 + tx * 4 + n, acc[m][n + 4]);
        }
    }
}

// ---------------- launch ----------------
extern "C" void kernel_launch(void* const* d_in, const int* in_sizes, int n_in,
                              void* d_out, int out_size) {
    const float* x     = (const float*)d_in[0];
    const float* w_ih0 = (const float*)d_in[1];
    const float* w_hh0 = (const float*)d_in[2];
    const float* b_ih0 = (const float*)d_in[3];
    const float* b_hh0 = (const float*)d_in[4];
    const float* w_ih  = (const float*)d_in[5];
    const float* w_hh  = (const float*)d_in[6];
    const float* b_ih  = (const float*)d_in[7];
    const float* b_hh  = (const float*)d_in[8];
    const float* fc_w  = (const float*)d_in[9];
    const float* fc_b  = (const float*)d_in[10];
    float* out = (float*)d_out;

    cudaFuncSetAttribute(proj16, cudaFuncAttributeMaxDynamicSharedMemorySize, PROJ_SMEM);
    cudaFuncSetAttribute(recur16, cudaFuncAttributeMaxDynamicSharedMemorySize, RECUR_SMEM);

    prep_x<<<2048, 256>>>(x);
    prep_wi<<<4096, 256>>>(w_ih0, w_ih);
    prep_wr<<<4096, 256>>>(w_hh0, w_hh);
    prep_bias<<<64, 256>>>(b_ih0, b_hh0, b_ih, b_hh);

    for (int l = 0; l < LL; l++) {
        proj16<<<dim3(16, 512), 256, PROJ_SMEM>>>(l);
        recur16<<<dim3(16, 8), 256, RECUR_SMEM>>>(l);
    }

    fc_init<<<(BQ * CC + 255) / 256, 256>>>(fc_b, out);
    fc_kernel<<<dim3(BQ / 128, TT), 256>>>(fc_w, out);
}